// round 12
// baseline (speedup 1.0000x reference)
#include <cuda_runtime.h>
#include <math.h>

#define ATOMS 48
#define CAP   48           // per-species bucket capacity (worst case)
#define BLK   128
#define APB   2            // atoms per block
#define BSTR  193          // padded per-atom bucket stride (4*CAP + 1)
#define GBS   129          // gbuf stride (chunk 128 + pad)

// cos/sin of SHF_Z[z] = (2z+1)*pi/16
__device__ __constant__ float COSZ[8] = {
     0.98078528040323044913f,  0.83146961230254523708f,
     0.55557023301960222474f,  0.19509032201612826785f,
    -0.19509032201612826785f, -0.55557023301960222474f,
    -0.83146961230254523708f, -0.98078528040323044913f };
__device__ __constant__ float SINZ[8] = {
     0.19509032201612826785f,  0.55557023301960222474f,
     0.83146961230254523708f,  0.98078528040323044913f,
     0.98078528040323044913f,  0.83146961230254523708f,
     0.55557023301960222474f,  0.19509032201612826785f };

// PAIR_IDX for 4 species (upper-triangular enumeration, symmetric)
__device__ __constant__ int PAIRT[4][4] = {
    {0,1,2,3},{1,4,5,6},{2,5,7,8},{3,6,8,9} };

// ---- packed fp32x2 helpers (sm_103a FFMA2/FMUL2 — PTX-only) ----
typedef unsigned long long u64;
__device__ __forceinline__ u64 pack2(float lo, float hi) {
    u64 r; asm("mov.b64 %0,{%1,%2};" : "=l"(r) : "f"(lo), "f"(hi)); return r;
}
__device__ __forceinline__ void unpack2(u64 v, float& lo, float& hi) {
    asm("mov.b64 {%0,%1},%2;" : "=f"(lo), "=f"(hi) : "l"(v));
}
__device__ __forceinline__ u64 fma2(u64 a, u64 b, u64 c) {
    u64 d; asm("fma.rn.f32x2 %0,%1,%2,%3;" : "=l"(d) : "l"(a), "l"(b), "l"(c)); return d;
}
__device__ __forceinline__ u64 mul2(u64 a, u64 b) {
    u64 d; asm("mul.rn.f32x2 %0,%1,%2;" : "=l"(d) : "l"(a), "l"(b)); return d;
}

__global__ void __launch_bounds__(BLK)
aev_kernel(const int* __restrict__ species, const float* __restrict__ coords,
           float* __restrict__ aev_out, float* __restrict__ sp_out)
{
    const int i0  = blockIdx.x * APB;  // first atom of this block
    const int b   = blockIdx.y;        // batch
    const int A   = ATOMS;
    const int tid = threadIdx.x;

    __shared__ float cx[ATOMS], cy[ATOMS], cz[ATOMS];
    __shared__ int   sp[ATOMS];
    __shared__ float4 bvec[APB*BSTR];   // (vx, vy, vz, d) angular buckets
    __shared__ float2 bsc[APB*BSTR];    // (sqrt(0.95)/d, fc_a)
    __shared__ float2 rpak[APB*4*CAP];  // (d, 0.25*fc_r) radial buckets
    __shared__ int   cnt[APB][4], rcnt[APB][4];
    __shared__ int   jlist[APB*CAP];    // slot(8b) | sj<<8 | atom<<10
    __shared__ int   Mtot;
    __shared__ int   gcnt[2*10];        // per-chunk class counters (atom,pair)
    __shared__ unsigned char glistP[2*10][BLK];
    __shared__ float gbuf[32 * GBS];    // [feature][local group] scratch

    const float* cb = coords + (size_t)b * A * 3;
    if (tid < A) {
        cx[tid] = cb[tid*3 + 0];
        cy[tid] = cb[tid*3 + 1];
        cz[tid] = cb[tid*3 + 2];
        sp[tid] = species[b*A + tid];
    }
    if (tid < 8)  { cnt[tid>>2][tid&3] = 0; rcnt[tid>>2][tid&3] = 0; }
    if (tid == 8) Mtot = 0;
    __syncthreads();

    // ---- phase 1: distances, bucketed neighbor lists (2 atoms x 48 j) ----
    if (tid < APB * A) {
        const int a  = tid / A;
        const int j  = tid - a * A;
        const int ia = i0 + a;
        if (j != ia) {
            float dx = cx[j] - cx[ia];
            float dy = cy[j] - cy[ia];
            float dz = cz[j] - cz[ia];
            float d  = sqrtf(dx*dx + dy*dy + dz*dz);
            int   s  = sp[j];
            if (d <= 5.2f) {
                float fcr = 0.5f * cospif(d / 5.2f) + 0.5f;
                int m = atomicAdd(&rcnt[a][s], 1);
                rpak[a*4*CAP + s*CAP + m] = make_float2(d, 0.25f * fcr);
            }
            if (d <= 3.5f) {
                float fca = 0.5f * cospif(d / 3.5f) + 0.5f;
                int m    = atomicAdd(&cnt[a][s], 1);
                int slot = s*CAP + m;                   // < 192, fits 8 bits
                bvec[a*BSTR + slot] = make_float4(dx, dy, dz, d);
                // sqrt(0.95)/d so that js.x*ks.x carries the 0.95 factor
                bsc[a*BSTR + slot]  = make_float2(0.97467943448089633f / d, fca);
                int pos = atomicAdd(&Mtot, 1);
                jlist[pos] = slot | (s << 8) | (a << 10);
            }
        }
    }
    __syncthreads();

    // ---- phase 2/3 fused: chunks of 128 groups; gbuf STS flush; ----
    // feature gather accumulated in registers across chunks.
    // Ordered-pair sum with weight fc_j*fc_k equals the reference's
    // unordered sum with weight 2*fc_j*fc_k (integrand symmetric in j,k).
    const float K1 = __expf(-6.76f);   // exp step for the f2 recurrence
    const u64 half2 = pack2(0.5f, 0.5f);
    u64 czh[4], szh[4];                // half-folded rotation constants
    #pragma unroll
    for (int zp = 0; zp < 4; zp++) {
        czh[zp] = pack2(0.5f * COSZ[2*zp], 0.5f * COSZ[2*zp+1]);
        szh[zp] = pack2(0.5f * SINZ[2*zp], 0.5f * SINZ[2*zp+1]);
    }

    const int Mc = Mtot;
    const int G  = 4 * Mc;             // groups: (sk-major, combined jlist)

    float racc[5];                     // angular features, 640 over 128 threads
    #pragma unroll
    for (int it = 0; it < 5; it++) racc[it] = 0.0f;

    for (int c0 = 0; c0 < G; c0 += BLK) {
        if (tid < 20) gcnt[tid] = 0;
        __syncthreads();

        const int g = c0 + tid;
        if (g < G) {
            const int sk    = g / Mc;
            const int idx   = g - sk * Mc;
            const int jid   = jlist[idx];
            const int jslot = jid & 255;
            const int sj    = (jid >> 8) & 3;
            const int a     = jid >> 10;
            const int ab    = a * BSTR;

            const float4 jv = bvec[ab + jslot];
            const float2 js = bsc[ab + jslot];

            u64 acc2[16];              // [a][zpair] packed fp32x2
            #pragma unroll
            for (int q = 0; q < 16; q++) acc2[q] = 0ull;

            const int n    = cnt[a][sk];
            const int base = ab + sk * CAP;
            #pragma unroll 2
            for (int m = 0; m < n; m++) {
                const int kslot = base + m;
                float4 kv = bvec[kslot];
                float2 ks = bsc[kslot];
                float dot = jv.x*kv.x + jv.y*kv.y + jv.z*kv.z;
                float ct  = dot * js.x * ks.x;            // carries 0.95
                float st  = sqrtf(fmaxf(1.0f - ct*ct, 0.0f));
                float avg = 0.5f * (jv.w + kv.w);
                float wgt = (kslot == ab + jslot) ? 0.0f : js.y * ks.y;

                // f2v[a] = w*exp(-8*(u-0.65a)^2), exact geometric recurrence
                float u   = avg - 0.9f;
                float f0  = wgt * __expf(-8.0f * u * u);
                float r   = __expf(fmaf(10.4f, u, -3.38f));
                float f1v = f0 * r;
                float r2  = r * K1;
                float f2v = f1v * r2;
                float r3  = r2 * K1;
                float f3v = f2v * r3;

                u64 ct2 = pack2(ct, ct);
                u64 st2 = pack2(st, st);
                u64 fp0 = pack2(f0,  f0);
                u64 fp1 = pack2(f1v, f1v);
                u64 fp2 = pack2(f2v, f2v);
                u64 fp3 = pack2(f3v, f3v);

                #pragma unroll
                for (int zp = 0; zp < 4; zp++) {
                    // b1 = 0.5 + 0.5*(ct*Cz + st*Sz)  (2 packed FMAs)
                    u64 b1  = fma2(ct2, czh[zp], fma2(st2, szh[zp], half2));
                    u64 b2  = mul2(b1, b1);
                    u64 b4  = mul2(b2, b2);
                    u64 b8  = mul2(b4, b4);
                    u64 b16 = mul2(b8, b8);
                    u64 f1p = mul2(b16, b16);             // ((1+c)/2)^32
                    acc2[0*4 + zp] = fma2(fp0, f1p, acc2[0*4 + zp]);
                    acc2[1*4 + zp] = fma2(fp1, f1p, acc2[1*4 + zp]);
                    acc2[2*4 + zp] = fma2(fp2, f1p, acc2[2*4 + zp]);
                    acc2[3*4 + zp] = fma2(fp3, f1p, acc2[3*4 + zp]);
                }
            }

            const int pcls = a * 10 + PAIRT[sj][sk];
            int mm = atomicAdd(&gcnt[pcls], 1);
            glistP[pcls][mm] = (unsigned char)tid;
            #pragma unroll
            for (int aa = 0; aa < 4; aa++)
                #pragma unroll
                for (int zp = 0; zp < 4; zp++) {
                    float lo, hi;
                    unpack2(acc2[aa*4 + zp], lo, hi);
                    gbuf[(aa*8 + 2*zp    ) * GBS + tid] = lo;
                    gbuf[(aa*8 + 2*zp + 1) * GBS + tid] = hi;
                }
        }
        __syncthreads();

        // gather: feature f = it*BLK + tid over (atom, pair-class, q)
        #pragma unroll
        for (int it = 0; it < 5; it++) {
            const int f = it * BLK + tid;      // < 640
            const int a    = f / 320;
            const int rem  = f - a * 320;
            const int pcls = a * 10 + (rem >> 5);
            const int q    = rem & 31;
            const int nm = gcnt[pcls];
            float s = 0.0f;
            for (int m = 0; m < nm; m++) {
                int lg = glistP[pcls][m];      // broadcast
                s += gbuf[q * GBS + lg];       // conflict-free: lanes consec q
            }
            racc[it] += s;
        }
        __syncthreads();
    }

    // ---- output ----
    // radial: feature (a, s, r) — exactly 128 features, one per thread
    {
        const int a = tid >> 6;
        const int s = (tid >> 4) & 3;
        const int r = tid & 15;
        const float shf = 0.9f + 0.26875f * (float)r;
        const int n = rcnt[a][s];
        float acc = 0.0f;
        for (int m = 0; m < n; m++) {
            float2 v = rpak[a*4*CAP + s*CAP + m];  // broadcast in 16-lane grp
            float u = v.x - shf;
            acc += v.y * __expf(-16.0f * u * u);
        }
        aev_out[(size_t)(b * A + i0 + a) * 384 + s*16 + r] = acc;
    }

    // angular: write register accumulators
    #pragma unroll
    for (int it = 0; it < 5; it++) {
        const int f = it * BLK + tid;
        const int a   = f / 320;
        const int rem = f - a * 320;
        aev_out[(size_t)(b * A + i0 + a) * 384 + 64 + rem] = racc[it];
    }

    if (sp_out != nullptr && tid < APB)
        sp_out[b * A + i0 + tid] = (float)sp[i0 + tid];
}

extern "C" void kernel_launch(void* const* d_in, const int* in_sizes, int n_in,
                              void* d_out, int out_size)
{
    const int*   species = (const int*)d_in[0];
    const float* coords  = (const float*)d_in[1];

    const int BA = in_sizes[0];     // B*A
    const int A  = ATOMS;           // 48 per reference
    const int B  = BA / A;
    const int aev_total = BA * 384;

    float* out    = (float*)d_out;
    float* sp_out = nullptr;
    float* aev    = out;
    if (out_size >= aev_total + BA) {   // tuple output: species first, then aevs
        sp_out = out;
        aev    = out + BA;
    }

    dim3 grid(A / APB, B);
    aev_kernel<<<grid, BLK>>>(species, coords, aev, sp_out);
}